// round 8
// baseline (speedup 1.0000x reference)
#include <cuda_runtime.h>
#include <cuda_fp16.h>
#include <math.h>

#define NJ   14
#define ELEM (NJ * 3)      // 42 floats per element per tensor
#define TPB  128
#define ROW  43            // padded half2 row (gcd(43,32)=1 -> conflict-free)

__device__ __forceinline__ float fast_sqrt(float x) {
    return x * rsqrtf(x + 1e-30f);
}

// Branchless Jacobi rotation, 2 MUFUs deep, division-free.
__device__ __forceinline__ void jacobi_rot(float A[3][3], float V[3][3], int p, int q) {
    float apq = A[p][q];
    float app = A[p][p], aqq = A[q][q];
    float h = aqq - app;
    float w = rsqrtf(h * h + 4.0f * apq * apq + 1e-38f);
    float sgn = copysignf(1.0f, h);
    float cos2t = fminf(fabsf(h) * w, 1.0f);
    float sin2t = 2.0f * apq * w * sgn;
    float c2 = 0.5f * (1.0f + cos2t);
    float invc = rsqrtf(c2);
    float c = c2 * invc;
    float s = 0.5f * sin2t * invc;
    int r = 3 - p - q;
    float arp = A[r][p], arq = A[r][q];
    float narp = c * arp - s * arq;
    float narq = s * arp + c * arq;
    A[r][p] = narp; A[p][r] = narp;
    A[r][q] = narq; A[q][r] = narq;
    float napp = c * c * app - 2.0f * s * c * apq + s * s * aqq;
    float naqq = s * s * app + 2.0f * s * c * apq + c * c * aqq;
    A[p][p] = napp; A[q][q] = naqq;
    A[p][q] = 0.0f; A[q][p] = 0.0f;
#pragma unroll
    for (int i = 0; i < 3; i++) {
        float vip = V[i][p], viq = V[i][q];
        V[i][p] = c * vip - s * viq;
        V[i][q] = s * vip + c * viq;
    }
}

__global__ void __launch_bounds__(TPB, 8)
pampjpe_kernel(const float* __restrict__ pred,
               const float* __restrict__ gt,
               float* __restrict__ out, int B)
{
    // Packed staging: spg[e*ROW + k] = half2( pred[e][k], gt[e][k] )
    __shared__ __half2 spg[TPB * ROW];

    const int base = blockIdx.x * TPB;
    const int tid  = threadIdx.x;
    const int valid = min(TPB, B - base);
    const int total = valid * ELEM;

    const float* __restrict__ pbase = pred + (size_t)base * ELEM;
    const float* __restrict__ gbase = gt   + (size_t)base * ELEM;

    if (valid == TPB) {
        const int total4 = (TPB * ELEM) / 4;   // 1344 float4 per tensor
        const float4* __restrict__ p4 = (const float4*)pbase;
        const float4* __restrict__ g4 = (const float4*)gbase;
#pragma unroll 3
        for (int i4 = tid; i4 < total4; i4 += TPB) {
            float4 vp = p4[i4];
            float4 vg = g4[i4];
            int idx = i4 * 4;
            float ap[4] = {vp.x, vp.y, vp.z, vp.w};
            float ag[4] = {vg.x, vg.y, vg.z, vg.w};
#pragma unroll
            for (int c = 0; c < 4; c++) {
                int id = idx + c;
                int e = id / ELEM;
                int k = id - e * ELEM;
                spg[e * ROW + k] = __floats2half2_rn(ap[c], ag[c]);
            }
        }
    } else {
        for (int i = tid; i < total; i += TPB) {
            int e = i / ELEM;
            int k = i - e * ELEM;
            spg[e * ROW + k] = __floats2half2_rn(pbase[i], gbase[i]);
        }
    }
    __syncthreads();

    if (tid >= valid) return;

    const __half2* D = &spg[tid * ROW];

    // Means
    float mu1[3] = {0.f, 0.f, 0.f};
    float mu2[3] = {0.f, 0.f, 0.f};
#pragma unroll
    for (int j = 0; j < NJ; j++) {
#pragma unroll
        for (int a = 0; a < 3; a++) {
            float2 pg = __half22float2(D[j * 3 + a]);
            mu1[a] += pg.x;
            mu2[a] += pg.y;
        }
    }
    const float invJ = 1.0f / (float)NJ;
#pragma unroll
    for (int a = 0; a < 3; a++) { mu1[a] *= invJ; mu2[a] *= invJ; }

    // Cross-covariance + var1
    float K[3][3] = {{0}};
    float var1 = 0.f;
#pragma unroll
    for (int j = 0; j < NJ; j++) {
        float x[3], y[3];
#pragma unroll
        for (int a = 0; a < 3; a++) {
            float2 pg = __half22float2(D[j * 3 + a]);
            x[a] = pg.x - mu1[a];
            y[a] = pg.y - mu2[a];
            var1 += x[a] * x[a];
        }
#pragma unroll
        for (int a = 0; a < 3; a++)
#pragma unroll
            for (int b = 0; b < 3; b++)
                K[a][b] += x[a] * y[b];
    }

    // A = K^T K (symmetric)
    float A[3][3];
#pragma unroll
    for (int i = 0; i < 3; i++)
#pragma unroll
        for (int j = i; j < 3; j++) {
            float acc = 0.f;
#pragma unroll
            for (int k = 0; k < 3; k++) acc += K[k][i] * K[k][j];
            A[i][j] = acc; A[j][i] = acc;
        }

    // Jacobi eigen-decomposition, 3 cyclic sweeps
    float V[3][3] = {{1.f, 0.f, 0.f}, {0.f, 1.f, 0.f}, {0.f, 0.f, 1.f}};
#pragma unroll
    for (int sweep = 0; sweep < 3; sweep++) {
        jacobi_rot(A, V, 0, 1);
        jacobi_rot(A, V, 0, 2);
        jacobi_rot(A, V, 1, 2);
    }

    float lam[3] = {A[0][0], A[1][1], A[2][2]};
#pragma unroll
    for (int a = 0; a < 2; a++)
#pragma unroll
        for (int b = a + 1; b < 3; b++)
            if (lam[a] < lam[b]) {
                float tl = lam[a]; lam[a] = lam[b]; lam[b] = tl;
#pragma unroll
                for (int r = 0; r < 3; r++) {
                    float tv = V[r][a]; V[r][a] = V[r][b]; V[r][b] = tv;
                }
            }

    float v0[3] = {V[0][0], V[1][0], V[2][0]};
    float v1[3] = {V[0][1], V[1][1], V[2][1]};
    float v2[3] = {v0[1]*v1[2] - v0[2]*v1[1],
                   v0[2]*v1[0] - v0[0]*v1[2],
                   v0[0]*v1[1] - v0[1]*v1[0]};

    float u0[3], u1[3];
#pragma unroll
    for (int i = 0; i < 3; i++) {
        u0[i] = K[i][0]*v0[0] + K[i][1]*v0[1] + K[i][2]*v0[2];
        u1[i] = K[i][0]*v1[0] + K[i][1]*v1[1] + K[i][2]*v1[2];
    }
    float n0 = rsqrtf(u0[0]*u0[0] + u0[1]*u0[1] + u0[2]*u0[2] + 1e-30f);
#pragma unroll
    for (int i = 0; i < 3; i++) u0[i] *= n0;
    float dot01 = u0[0]*u1[0] + u0[1]*u1[1] + u0[2]*u1[2];
#pragma unroll
    for (int i = 0; i < 3; i++) u1[i] -= dot01 * u0[i];
    float n1 = rsqrtf(u1[0]*u1[0] + u1[1]*u1[1] + u1[2]*u1[2] + 1e-30f);
#pragma unroll
    for (int i = 0; i < 3; i++) u1[i] *= n1;
    float u2[3] = {u0[1]*u1[2] - u0[2]*u1[1],
                   u0[2]*u1[0] - u0[0]*u1[2],
                   u0[0]*u1[1] - u0[1]*u1[0]};

    float R[3][3];
#pragma unroll
    for (int i = 0; i < 3; i++)
#pragma unroll
        for (int j = 0; j < 3; j++)
            R[i][j] = v0[i]*u0[j] + v1[i]*u1[j] + v2[i]*u2[j];

    float trRK = 0.f;
#pragma unroll
    for (int i = 0; i < 3; i++)
#pragma unroll
        for (int k = 0; k < 3; k++)
            trRK += R[i][k] * K[k][i];
    float scale = __fdividef(trRK, var1 + 1e-30f);

    // Per-joint error, averaged
    float acc = 0.f;
#pragma unroll
    for (int j = 0; j < NJ; j++) {
        float x[3], y[3];
#pragma unroll
        for (int a = 0; a < 3; a++) {
            float2 pg = __half22float2(D[j * 3 + a]);
            x[a] = pg.x - mu1[a];
            y[a] = pg.y - mu2[a];
        }
        float d0 = scale * (R[0][0]*x[0] + R[0][1]*x[1] + R[0][2]*x[2]) - y[0];
        float d1 = scale * (R[1][0]*x[0] + R[1][1]*x[1] + R[1][2]*x[2]) - y[1];
        float d2 = scale * (R[2][0]*x[0] + R[2][1]*x[1] + R[2][2]*x[2]) - y[2];
        acc += fast_sqrt(d0*d0 + d1*d1 + d2*d2);
    }
    out[base + tid] = acc * invJ;
}

extern "C" void kernel_launch(void* const* d_in, const int* in_sizes, int n_in,
                              void* d_out, int out_size) {
    const float* pred = (const float*)d_in[0];
    const float* gt   = (const float*)d_in[1];
    float* out = (float*)d_out;
    int B = in_sizes[0] / ELEM;
    int grid = (B + TPB - 1) / TPB;
    pampjpe_kernel<<<grid, TPB>>>(pred, gt, out, B);
}

// round 9
// speedup vs baseline: 1.2027x; 1.2027x over previous
#include <cuda_runtime.h>
#include <math.h>

#define NJ   14
#define ELEM (NJ * 3)      // 42 floats per element per tensor
#define TPB  128
#define ROW  43            // padded smem row (gcd(43,32)=1 -> conflict-free)

__device__ __forceinline__ float fast_sqrt(float x) {
    return x * rsqrtf(x + 1e-30f);
}

// Branchless Jacobi rotation, 2 MUFUs deep, division-free.
__device__ __forceinline__ void jacobi_rot(float A[3][3], float V[3][3], int p, int q) {
    float apq = A[p][q];
    float app = A[p][p], aqq = A[q][q];
    float h = aqq - app;
    float w = rsqrtf(h * h + 4.0f * apq * apq + 1e-38f);
    float sgn = copysignf(1.0f, h);
    float cos2t = fminf(fabsf(h) * w, 1.0f);
    float sin2t = 2.0f * apq * w * sgn;
    float c2 = 0.5f * (1.0f + cos2t);
    float invc = rsqrtf(c2);
    float c = c2 * invc;
    float s = 0.5f * sin2t * invc;
    int r = 3 - p - q;
    float arp = A[r][p], arq = A[r][q];
    float narp = c * arp - s * arq;
    float narq = s * arp + c * arq;
    A[r][p] = narp; A[p][r] = narp;
    A[r][q] = narq; A[q][r] = narq;
    float napp = c * c * app - 2.0f * s * c * apq + s * s * aqq;
    float naqq = s * s * app + 2.0f * s * c * apq + c * c * aqq;
    A[p][p] = napp; A[q][q] = naqq;
    A[p][q] = 0.0f; A[q][p] = 0.0f;
#pragma unroll
    for (int i = 0; i < 3; i++) {
        float vip = V[i][p], viq = V[i][q];
        V[i][p] = c * vip - s * viq;
        V[i][q] = s * vip + c * viq;
    }
}

__global__ void __launch_bounds__(TPB, 5)
pampjpe_kernel(const float* __restrict__ pred,
               const float* __restrict__ gt,
               float* __restrict__ out, int B)
{
    __shared__ float sp[TPB * ROW];
    __shared__ float sg[TPB * ROW];

    const int base = blockIdx.x * TPB;
    const int tid  = threadIdx.x;
    const int valid = min(TPB, B - base);
    const int total = valid * ELEM;

    const float* __restrict__ pbase = pred + (size_t)base * ELEM;
    const float* __restrict__ gbase = gt   + (size_t)base * ELEM;

    if (valid == TPB) {
        const int total4 = (TPB * ELEM) / 4;   // 1344 float4 per tensor
        const float4* __restrict__ p4 = (const float4*)pbase;
        const float4* __restrict__ g4 = (const float4*)gbase;
#pragma unroll 3
        for (int i4 = tid; i4 < total4; i4 += TPB) {
            float4 vp = p4[i4];
            float4 vg = g4[i4];
            int idx = i4 * 4;
            float ap[4] = {vp.x, vp.y, vp.z, vp.w};
            float ag[4] = {vg.x, vg.y, vg.z, vg.w};
#pragma unroll
            for (int c = 0; c < 4; c++) {
                int id = idx + c;
                int e = id / ELEM;
                int k = id - e * ELEM;
                sp[e * ROW + k] = ap[c];
                sg[e * ROW + k] = ag[c];
            }
        }
    } else {
        for (int i = tid; i < total; i += TPB) {
            int e = i / ELEM;
            int k = i - e * ELEM;
            sp[e * ROW + k] = pbase[i];
            sg[e * ROW + k] = gbase[i];
        }
    }
    __syncthreads();

    if (tid >= valid) return;

    const float* P = &sp[tid * ROW];
    const float* G = &sg[tid * ROW];

    // ---- single fused pass: uncentered moments ----
    // sp_s = sum p, sg_s = sum g, M = sum p g^T, sq = sum |p|^2
    float sp_s[3] = {0.f, 0.f, 0.f};
    float sg_s[3] = {0.f, 0.f, 0.f};
    float M[3][3] = {{0}};
    float sq = 0.f;
#pragma unroll
    for (int j = 0; j < NJ; j++) {
        float p[3], g[3];
#pragma unroll
        for (int a = 0; a < 3; a++) {
            p[a] = P[j * 3 + a];
            g[a] = G[j * 3 + a];
            sp_s[a] += p[a];
            sg_s[a] += g[a];
            sq += p[a] * p[a];
        }
#pragma unroll
        for (int a = 0; a < 3; a++)
#pragma unroll
            for (int b = 0; b < 3; b++)
                M[a][b] += p[a] * g[b];
    }
    const float invJ = 1.0f / (float)NJ;
    float mu1[3], mu2[3];
#pragma unroll
    for (int a = 0; a < 3; a++) { mu1[a] = sp_s[a] * invJ; mu2[a] = sg_s[a] * invJ; }

    // Centering corrections: K = M - sp_s * mu2^T ; var1 = sq - sp_s . mu1
    float K[3][3];
#pragma unroll
    for (int a = 0; a < 3; a++)
#pragma unroll
        for (int b = 0; b < 3; b++)
            K[a][b] = M[a][b] - sp_s[a] * mu2[b];
    float var1 = sq - (sp_s[0] * mu1[0] + sp_s[1] * mu1[1] + sp_s[2] * mu1[2]);

    // A = K^T K (symmetric)
    float A[3][3];
#pragma unroll
    for (int i = 0; i < 3; i++)
#pragma unroll
        for (int j = i; j < 3; j++) {
            float acc = 0.f;
#pragma unroll
            for (int k = 0; k < 3; k++) acc += K[k][i] * K[k][j];
            A[i][j] = acc; A[j][i] = acc;
        }

    // Jacobi eigen-decomposition, 3 cyclic sweeps
    float V[3][3] = {{1.f, 0.f, 0.f}, {0.f, 1.f, 0.f}, {0.f, 0.f, 1.f}};
#pragma unroll
    for (int sweep = 0; sweep < 3; sweep++) {
        jacobi_rot(A, V, 0, 1);
        jacobi_rot(A, V, 0, 2);
        jacobi_rot(A, V, 1, 2);
    }

    float lam[3] = {A[0][0], A[1][1], A[2][2]};
#pragma unroll
    for (int a = 0; a < 2; a++)
#pragma unroll
        for (int b = a + 1; b < 3; b++)
            if (lam[a] < lam[b]) {
                float tl = lam[a]; lam[a] = lam[b]; lam[b] = tl;
#pragma unroll
                for (int r = 0; r < 3; r++) {
                    float tv = V[r][a]; V[r][a] = V[r][b]; V[r][b] = tv;
                }
            }

    float v0[3] = {V[0][0], V[1][0], V[2][0]};
    float v1[3] = {V[0][1], V[1][1], V[2][1]};
    float v2[3] = {v0[1]*v1[2] - v0[2]*v1[1],
                   v0[2]*v1[0] - v0[0]*v1[2],
                   v0[0]*v1[1] - v0[1]*v1[0]};

    float u0[3], u1[3];
#pragma unroll
    for (int i = 0; i < 3; i++) {
        u0[i] = K[i][0]*v0[0] + K[i][1]*v0[1] + K[i][2]*v0[2];
        u1[i] = K[i][0]*v1[0] + K[i][1]*v1[1] + K[i][2]*v1[2];
    }
    float n0 = rsqrtf(u0[0]*u0[0] + u0[1]*u0[1] + u0[2]*u0[2] + 1e-30f);
#pragma unroll
    for (int i = 0; i < 3; i++) u0[i] *= n0;
    float dot01 = u0[0]*u1[0] + u0[1]*u1[1] + u0[2]*u1[2];
#pragma unroll
    for (int i = 0; i < 3; i++) u1[i] -= dot01 * u0[i];
    float n1 = rsqrtf(u1[0]*u1[0] + u1[1]*u1[1] + u1[2]*u1[2] + 1e-30f);
#pragma unroll
    for (int i = 0; i < 3; i++) u1[i] *= n1;
    float u2[3] = {u0[1]*u1[2] - u0[2]*u1[1],
                   u0[2]*u1[0] - u0[0]*u1[2],
                   u0[0]*u1[1] - u0[1]*u1[0]};

    float R[3][3];
#pragma unroll
    for (int i = 0; i < 3; i++)
#pragma unroll
        for (int j = 0; j < 3; j++)
            R[i][j] = v0[i]*u0[j] + v1[i]*u1[j] + v2[i]*u2[j];

    float trRK = 0.f;
#pragma unroll
    for (int i = 0; i < 3; i++)
#pragma unroll
        for (int k = 0; k < 3; k++)
            trRK += R[i][k] * K[k][i];
    float scale = __fdividef(trRK, var1 + 1e-30f);

    // Per-joint error with 2 partial accumulators (shorter FADD tail)
    float accA = 0.f, accB = 0.f;
#pragma unroll
    for (int j = 0; j < NJ; j += 2) {
#pragma unroll
        for (int u = 0; u < 2; u++) {
            int jj = j + u;
            float x[3], y[3];
#pragma unroll
            for (int a = 0; a < 3; a++) {
                x[a] = P[jj * 3 + a] - mu1[a];
                y[a] = G[jj * 3 + a] - mu2[a];
            }
            float d0 = scale * (R[0][0]*x[0] + R[0][1]*x[1] + R[0][2]*x[2]) - y[0];
            float d1 = scale * (R[1][0]*x[0] + R[1][1]*x[1] + R[1][2]*x[2]) - y[1];
            float d2 = scale * (R[2][0]*x[0] + R[2][1]*x[1] + R[2][2]*x[2]) - y[2];
            float e2 = fast_sqrt(d0*d0 + d1*d1 + d2*d2);
            if (u == 0) accA += e2; else accB += e2;
        }
    }
    out[base + tid] = (accA + accB) * invJ;
}

extern "C" void kernel_launch(void* const* d_in, const int* in_sizes, int n_in,
                              void* d_out, int out_size) {
    const float* pred = (const float*)d_in[0];
    const float* gt   = (const float*)d_in[1];
    float* out = (float*)d_out;
    int B = in_sizes[0] / ELEM;
    int grid = (B + TPB - 1) / TPB;
    pampjpe_kernel<<<grid, TPB>>>(pred, gt, out, B);
}

// round 10
// speedup vs baseline: 1.5006x; 1.2478x over previous
#include <cuda_runtime.h>
#include <math.h>

#define NJ   14
#define ELEM (NJ * 3)      // 42 floats per element per tensor
#define TPB  128
#define ROW  43            // padded smem row (gcd(43,32)=1 -> conflict-free)

__device__ __forceinline__ float fast_sqrt(float x) {
    return x * rsqrtf(x + 1e-30f);
}

// Branchless Jacobi rotation, 2 MUFUs deep, division-free.
__device__ __forceinline__ void jacobi_rot(float A[3][3], float V[3][3], int p, int q) {
    float apq = A[p][q];
    float app = A[p][p], aqq = A[q][q];
    float h = aqq - app;
    float w = rsqrtf(h * h + 4.0f * apq * apq + 1e-38f);
    float sgn = copysignf(1.0f, h);
    float cos2t = fminf(fabsf(h) * w, 1.0f);
    float sin2t = 2.0f * apq * w * sgn;
    float c2 = 0.5f * (1.0f + cos2t);
    float invc = rsqrtf(c2);
    float c = c2 * invc;
    float s = 0.5f * sin2t * invc;
    int r = 3 - p - q;
    float arp = A[r][p], arq = A[r][q];
    float narp = c * arp - s * arq;
    float narq = s * arp + c * arq;
    A[r][p] = narp; A[p][r] = narp;
    A[r][q] = narq; A[q][r] = narq;
    float napp = c * c * app - 2.0f * s * c * apq + s * s * aqq;
    float naqq = s * s * app + 2.0f * s * c * apq + c * c * aqq;
    A[p][p] = napp; A[q][q] = naqq;
    A[p][q] = 0.0f; A[q][p] = 0.0f;
#pragma unroll
    for (int i = 0; i < 3; i++) {
        float vip = V[i][p], viq = V[i][q];
        V[i][p] = c * vip - s * viq;
        V[i][q] = s * vip + c * viq;
    }
}

__global__ void __launch_bounds__(TPB, 5)
pampjpe_kernel(const float* __restrict__ pred,
               const float* __restrict__ gt,
               float* __restrict__ out, int B)
{
    __shared__ float sp[TPB * ROW];
    __shared__ float sg[TPB * ROW];

    const int base = blockIdx.x * TPB;
    const int tid  = threadIdx.x;
    const int valid = min(TPB, B - base);
    const int total = valid * ELEM;

    const float* __restrict__ pbase = pred + (size_t)base * ELEM;
    const float* __restrict__ gbase = gt   + (size_t)base * ELEM;

    if (valid == TPB) {
        const int total4 = (TPB * ELEM) / 4;   // 1344 float4 per tensor
        const float4* __restrict__ p4 = (const float4*)pbase;
        const float4* __restrict__ g4 = (const float4*)gbase;
#pragma unroll 3
        for (int i4 = tid; i4 < total4; i4 += TPB) {
            float4 vp = p4[i4];
            float4 vg = g4[i4];
            int idx = i4 * 4;
            float ap[4] = {vp.x, vp.y, vp.z, vp.w};
            float ag[4] = {vg.x, vg.y, vg.z, vg.w};
#pragma unroll
            for (int c = 0; c < 4; c++) {
                int id = idx + c;
                int e = id / ELEM;
                int k = id - e * ELEM;
                sp[e * ROW + k] = ap[c];
                sg[e * ROW + k] = ag[c];
            }
        }
    } else {
        for (int i = tid; i < total; i += TPB) {
            int e = i / ELEM;
            int k = i - e * ELEM;
            sp[e * ROW + k] = pbase[i];
            sg[e * ROW + k] = gbase[i];
        }
    }
    __syncthreads();

    if (tid >= valid) return;

    const float* P = &sp[tid * ROW];
    const float* G = &sg[tid * ROW];

    // Means
    float mu1[3] = {0.f, 0.f, 0.f};
    float mu2[3] = {0.f, 0.f, 0.f};
#pragma unroll
    for (int j = 0; j < NJ; j++) {
#pragma unroll
        for (int a = 0; a < 3; a++) {
            mu1[a] += P[j * 3 + a];
            mu2[a] += G[j * 3 + a];
        }
    }
    const float invJ = 1.0f / (float)NJ;
#pragma unroll
    for (int a = 0; a < 3; a++) { mu1[a] *= invJ; mu2[a] *= invJ; }

    // Cross-covariance K[a][b] = sum_j x_j[a]*y_j[b]; var1 = sum |x|^2
    float K[3][3] = {{0}};
    float var1 = 0.f;
#pragma unroll
    for (int j = 0; j < NJ; j++) {
        float x[3], y[3];
#pragma unroll
        for (int a = 0; a < 3; a++) {
            x[a] = P[j * 3 + a] - mu1[a];
            y[a] = G[j * 3 + a] - mu2[a];
            var1 += x[a] * x[a];
        }
#pragma unroll
        for (int a = 0; a < 3; a++)
#pragma unroll
            for (int b = 0; b < 3; b++)
                K[a][b] += x[a] * y[b];
    }

    // A = K^T K (symmetric)
    float A[3][3];
#pragma unroll
    for (int i = 0; i < 3; i++)
#pragma unroll
        for (int j = i; j < 3; j++) {
            float acc = 0.f;
#pragma unroll
            for (int k = 0; k < 3; k++) acc += K[k][i] * K[k][j];
            A[i][j] = acc; A[j][i] = acc;
        }

    // Jacobi eigen-decomposition: 2 cyclic sweeps + (0,1) touch-up = 7 rotations
    float V[3][3] = {{1.f, 0.f, 0.f}, {0.f, 1.f, 0.f}, {0.f, 0.f, 1.f}};
#pragma unroll
    for (int sweep = 0; sweep < 2; sweep++) {
        jacobi_rot(A, V, 0, 1);
        jacobi_rot(A, V, 0, 2);
        jacobi_rot(A, V, 1, 2);
    }
    jacobi_rot(A, V, 0, 1);

    float lam[3] = {A[0][0], A[1][1], A[2][2]};
    // Sort eigenpairs descending
#pragma unroll
    for (int a = 0; a < 2; a++)
#pragma unroll
        for (int b = a + 1; b < 3; b++)
            if (lam[a] < lam[b]) {
                float tl = lam[a]; lam[a] = lam[b]; lam[b] = tl;
#pragma unroll
                for (int r = 0; r < 3; r++) {
                    float tv = V[r][a]; V[r][a] = V[r][b]; V[r][b] = tv;
                }
            }

    // v0, v1 = top right singular vectors of K; v2 = v0 x v1 forces det(V)=+1
    float v0[3] = {V[0][0], V[1][0], V[2][0]};
    float v1[3] = {V[0][1], V[1][1], V[2][1]};
    float v2[3] = {v0[1]*v1[2] - v0[2]*v1[1],
                   v0[2]*v1[0] - v0[0]*v1[2],
                   v0[0]*v1[1] - v0[1]*v1[0]};

    // u0 = normalize(K v0); u1 = normalize(K v1 - (u0.Kv1)u0); u2 = u0 x u1
    float u0[3], u1[3];
#pragma unroll
    for (int i = 0; i < 3; i++) {
        u0[i] = K[i][0]*v0[0] + K[i][1]*v0[1] + K[i][2]*v0[2];
        u1[i] = K[i][0]*v1[0] + K[i][1]*v1[1] + K[i][2]*v1[2];
    }
    float n0 = rsqrtf(u0[0]*u0[0] + u0[1]*u0[1] + u0[2]*u0[2] + 1e-30f);
#pragma unroll
    for (int i = 0; i < 3; i++) u0[i] *= n0;
    float dot01 = u0[0]*u1[0] + u0[1]*u1[1] + u0[2]*u1[2];
#pragma unroll
    for (int i = 0; i < 3; i++) u1[i] -= dot01 * u0[i];
    float n1 = rsqrtf(u1[0]*u1[0] + u1[1]*u1[1] + u1[2]*u1[2] + 1e-30f);
#pragma unroll
    for (int i = 0; i < 3; i++) u1[i] *= n1;
    float u2[3] = {u0[1]*u1[2] - u0[2]*u1[1],
                   u0[2]*u1[0] - u0[0]*u1[2],
                   u0[0]*u1[1] - u0[1]*u1[0]};

    // R = v0 u0^T + v1 u1^T + v2 u2^T
    float R[3][3];
#pragma unroll
    for (int i = 0; i < 3; i++)
#pragma unroll
        for (int j = 0; j < 3; j++)
            R[i][j] = v0[i]*u0[j] + v1[i]*u1[j] + v2[i]*u2[j];

    // scale = trace(R K) / var1
    float trRK = 0.f;
#pragma unroll
    for (int i = 0; i < 3; i++)
#pragma unroll
        for (int k = 0; k < 3; k++)
            trRK += R[i][k] * K[k][i];
    float scale = __fdividef(trRK, var1 + 1e-30f);

    // Per-joint error, averaged
    float acc = 0.f;
#pragma unroll
    for (int j = 0; j < NJ; j++) {
        float x[3], y[3];
#pragma unroll
        for (int a = 0; a < 3; a++) {
            x[a] = P[j * 3 + a] - mu1[a];
            y[a] = G[j * 3 + a] - mu2[a];
        }
        float d0 = scale * (R[0][0]*x[0] + R[0][1]*x[1] + R[0][2]*x[2]) - y[0];
        float d1 = scale * (R[1][0]*x[0] + R[1][1]*x[1] + R[1][2]*x[2]) - y[1];
        float d2 = scale * (R[2][0]*x[0] + R[2][1]*x[1] + R[2][2]*x[2]) - y[2];
        acc += fast_sqrt(d0*d0 + d1*d1 + d2*d2);
    }
    out[base + tid] = acc * invJ;
}

extern "C" void kernel_launch(void* const* d_in, const int* in_sizes, int n_in,
                              void* d_out, int out_size) {
    const float* pred = (const float*)d_in[0];
    const float* gt   = (const float*)d_in[1];
    float* out = (float*)d_out;
    int B = in_sizes[0] / ELEM;
    int grid = (B + TPB - 1) / TPB;
    pampjpe_kernel<<<grid, TPB>>>(pred, gt, out, B);
}